// round 1
// baseline (speedup 1.0000x reference)
#include <cuda_runtime.h>

// Problem constants
#define T_STEPS 512
#define BATCH   256
#define DIM     256
#define HID     256
#define OUTD    64
#define KTOT    512   // D + H
#define KC      64    // K chunk staged in smem
#define NCH     (KTOT / KC)
#define BR      32    // batch rows per CTA
#define BJ      16    // h-columns per CTA (x4 gates = 64 gate cols)
#define PAD     66    // smem row pitch (floats): even (8B aligned), odd in 8B units -> conflict-free LDS.64

// Persistent state (allocation-free scratch). h double-buffered to avoid
// read/write races across CTAs within a step; c is owned per (b,j) tile.
__device__ float g_h[2][BATCH * HID];
__device__ float g_c[BATCH * HID];

typedef unsigned long long u64;

// Packed fp32x2 FMA (2x FFMA throughput on sm_103a; only reachable via PTX).
__device__ __forceinline__ u64 ffma2(u64 a, u64 b, u64 c) {
    u64 d;
    asm("fma.rn.f32x2 %0, %1, %2, %3;" : "=l"(d) : "l"(a), "l"(b), "l"(c));
    return d;
}

__device__ __forceinline__ float f2sum(u64 v) {
    float lo = __uint_as_float((unsigned)(v & 0xffffffffull));
    float hi = __uint_as_float((unsigned)(v >> 32));
    return lo + hi;
}

__device__ __forceinline__ float sigmoid_f(float x) {
    return 1.0f / (1.0f + __expf(-x));
}
__device__ __forceinline__ float tanh_f(float x) {
    // 1 - 2/(e^{2x}+1): saturates correctly for |x| large (no inf/inf)
    float e = __expf(2.0f * x);
    return 1.0f - 2.0f / (e + 1.0f);
}

__global__ void zero_state() {
    int i = blockIdx.x * blockDim.x + threadIdx.x;
    if (i < BATCH * HID) {
        g_h[0][i] = 0.0f;
        g_c[i] = 0.0f;
    }
}

// One LSTM timestep: gates = [x_t, h] @ [Wx;Wh] + b, then elementwise update.
// Grid: (16 col-tiles, 8 row-tiles), 256 threads.
__global__ __launch_bounds__(256) void lstm_step(
    const float* __restrict__ x,
    const int*   __restrict__ lengths,
    const float* __restrict__ Wf, const float* __restrict__ bf,
    const float* __restrict__ Wi, const float* __restrict__ bi,
    const float* __restrict__ Wc, const float* __restrict__ bc,
    const float* __restrict__ Wo, const float* __restrict__ bo,
    int t)
{
    __shared__ __align__(16) float sA[BR][PAD];      // [row][k] within chunk
    __shared__ __align__(16) float sW[4 * BJ][PAD];  // [gate*16+jj][k] within chunk

    const int tid = threadIdx.x;
    const int jj  = tid & 15;        // local h-col
    const int rr  = tid >> 4;        // 0..15 -> rows rr and rr+16
    const int j0  = blockIdx.x * BJ;
    const int b0  = blockIdx.y * BR;

    const float* __restrict__ hin  = g_h[t & 1];
    float*       __restrict__ hout = g_h[(t + 1) & 1];

    u64 acc[2][4];
#pragma unroll
    for (int r = 0; r < 2; ++r)
#pragma unroll
        for (int g = 0; g < 4; ++g) acc[r][g] = 0ull;

    // W-loader mapping: thread -> (gate, k-within-chunk)
    const int gsel = tid >> 6;   // 0..3
    const int kkw  = tid & 63;   // 0..63
    const float* __restrict__ Wg = (gsel == 0) ? Wf : (gsel == 1) ? Wi : (gsel == 2) ? Wc : Wo;

    for (int ch = 0; ch < NCH; ++ch) {
        // ---- stage A chunk: rows = batch rows, cols = K chunk (x for k<256, h for k>=256)
#pragma unroll
        for (int it = 0; it < 2; ++it) {
            int idx4 = tid + it * 256;        // 512 float4's per chunk
            int r    = idx4 >> 4;             // 16 float4 per row
            int kk   = (idx4 & 15) * 4;
            int kg   = ch * KC + kk;
            const float* src = (kg < DIM)
                ? (x + ((size_t)t * BATCH + (b0 + r)) * DIM + kg)
                : (hin + (size_t)(b0 + r) * HID + (kg - DIM));
            float4 v = *(const float4*)src;
            float2* d = (float2*)&sA[r][kk];  // 8B aligned (kk mult of 4, pitch even)
            d[0] = make_float2(v.x, v.y);
            d[1] = make_float2(v.z, v.w);
        }
        // ---- stage W chunk: sW[g*16+jj][kk] = Wg[kglob][j0+jj]
        {
            int kg = ch * KC + kkw;
            const float4* p = (const float4*)(Wg + (size_t)kg * HID + j0);
#pragma unroll
            for (int m = 0; m < 4; ++m) {
                float4 v = p[m];
                sW[gsel * 16 + m * 4 + 0][kkw] = v.x;
                sW[gsel * 16 + m * 4 + 1][kkw] = v.y;
                sW[gsel * 16 + m * 4 + 2][kkw] = v.z;
                sW[gsel * 16 + m * 4 + 3][kkw] = v.w;
            }
        }
        __syncthreads();

        // ---- compute: 32 k-pairs, 8 ffma2 + 6 LDS.64 each
#pragma unroll 8
        for (int kp = 0; kp < KC / 2; ++kp) {
            u64 a0 = *(const u64*)&sA[rr][kp * 2];
            u64 a1 = *(const u64*)&sA[rr + 16][kp * 2];
#pragma unroll
            for (int g = 0; g < 4; ++g) {
                u64 w2 = *(const u64*)&sW[g * 16 + jj][kp * 2];
                acc[0][g] = ffma2(a0, w2, acc[0][g]);
                acc[1][g] = ffma2(a1, w2, acc[1][g]);
            }
        }
        __syncthreads();
    }

    // ---- epilogue: all 4 gates for (b, j) live in this thread's registers
    const int j = j0 + jj;
    const float bfv = bf[j], biv = bi[j], bcv = bc[j], bov = bo[j];
#pragma unroll
    for (int r = 0; r < 2; ++r) {
        const int b = b0 + rr + r * 16;
        float fpre = f2sum(acc[r][0]) + bfv;
        float ipre = f2sum(acc[r][1]) + biv;
        float cpre = f2sum(acc[r][2]) + bcv;
        float opre = f2sum(acc[r][3]) + bov;
        float fg = sigmoid_f(fpre);
        float ig = sigmoid_f(ipre);
        float og = sigmoid_f(opre);
        float cc = tanh_f(cpre);

        size_t off = (size_t)b * HID + j;
        float cold = g_c[off];
        float cnew = fg * cold + ig * cc;
        float hnew = og * tanh_f(cnew);
        bool active = t < lengths[b];
        g_c[off]  = active ? cnew : cold;
        hout[off] = active ? hnew : hin[off];
    }
}

// y = h @ Wy + by ; also emit h (outputs are (y, h) concatenated).
__global__ void lstm_final(const float* __restrict__ Wy,
                           const float* __restrict__ by,
                           float* __restrict__ out,
                           int out_size)
{
    __shared__ float hrow[HID];
    const int b   = blockIdx.x;
    const int tid = threadIdx.x;   // 64 threads = OUTD

    const float* __restrict__ hfin = g_h[T_STEPS & 1];  // buffer 0 after 512 steps
    for (int k = tid; k < HID; k += OUTD) hrow[k] = hfin[(size_t)b * HID + k];
    __syncthreads();

    float acc = by[tid];
#pragma unroll 8
    for (int k = 0; k < HID; ++k) acc += hrow[k] * Wy[(size_t)k * OUTD + tid];
    out[(size_t)b * OUTD + tid] = acc;

    if (out_size >= BATCH * OUTD + BATCH * HID) {
        for (int k = tid; k < HID; k += OUTD)
            out[BATCH * OUTD + (size_t)b * HID + k] = hrow[k];
    }
}

extern "C" void kernel_launch(void* const* d_in, const int* in_sizes, int n_in,
                              void* d_out, int out_size) {
    const float* x       = (const float*)d_in[0];
    const int*   lengths = (const int*)  d_in[1];
    const float* Wf      = (const float*)d_in[2];
    const float* bf      = (const float*)d_in[3];
    const float* Wi      = (const float*)d_in[4];
    const float* bi      = (const float*)d_in[5];
    const float* Wc      = (const float*)d_in[6];
    const float* bc      = (const float*)d_in[7];
    const float* Wo      = (const float*)d_in[8];
    const float* bo      = (const float*)d_in[9];
    const float* Wy      = (const float*)d_in[10];
    const float* by      = (const float*)d_in[11];
    float* out = (float*)d_out;

    zero_state<<<128, 512>>>();
    for (int t = 0; t < T_STEPS; ++t) {
        lstm_step<<<dim3(HID / BJ, BATCH / BR), 256>>>(
            x, lengths, Wf, bf, Wi, bi, Wc, bc, Wo, bo, t);
    }
    lstm_final<<<BATCH, OUTD>>>(Wy, by, out, out_size);
}

// round 2
// speedup vs baseline: 1.0009x; 1.0009x over previous
#include <cuda_runtime.h>

// Problem constants
#define T_STEPS 512
#define BATCH   256
#define DIM     256
#define HID     256
#define OUTD    64
#define KTOT    512   // D + H
#define KC      64    // K chunk staged in smem
#define NCH     (KTOT / KC)
#define BR      32    // batch rows per CTA
#define BJ      16    // h-columns per CTA (x4 gates = 64 gate cols)
#define PAD     66    // smem row pitch (floats): even (8B aligned), odd in 8B units -> conflict-free LDS.64

// Persistent state (allocation-free scratch). h double-buffered to avoid
// read/write races across CTAs within a step; c is owned per (b,j) tile.
__device__ float g_h[2][BATCH * HID];
__device__ float g_c[BATCH * HID];

typedef unsigned long long u64;

// Packed fp32x2 FMA (2x FFMA throughput on sm_103a; only reachable via PTX).
__device__ __forceinline__ u64 ffma2(u64 a, u64 b, u64 c) {
    u64 d;
    asm("fma.rn.f32x2 %0, %1, %2, %3;" : "=l"(d) : "l"(a), "l"(b), "l"(c));
    return d;
}

__device__ __forceinline__ float f2sum(u64 v) {
    float lo = __uint_as_float((unsigned)(v & 0xffffffffull));
    float hi = __uint_as_float((unsigned)(v >> 32));
    return lo + hi;
}

__device__ __forceinline__ float sigmoid_f(float x) {
    return 1.0f / (1.0f + __expf(-x));
}
__device__ __forceinline__ float tanh_f(float x) {
    // 1 - 2/(e^{2x}+1): saturates correctly for |x| large (no inf/inf)
    float e = __expf(2.0f * x);
    return 1.0f - 2.0f / (e + 1.0f);
}

__global__ void zero_state() {
    int i = blockIdx.x * blockDim.x + threadIdx.x;
    if (i < BATCH * HID) {
        g_h[0][i] = 0.0f;
        g_c[i] = 0.0f;
    }
}

// One LSTM timestep: gates = [x_t, h] @ [Wx;Wh] + b, then elementwise update.
// Grid: (16 col-tiles, 8 row-tiles), 256 threads.
__global__ __launch_bounds__(256) void lstm_step(
    const float* __restrict__ x,
    const int*   __restrict__ lengths,
    const float* __restrict__ Wf, const float* __restrict__ bf,
    const float* __restrict__ Wi, const float* __restrict__ bi,
    const float* __restrict__ Wc, const float* __restrict__ bc,
    const float* __restrict__ Wo, const float* __restrict__ bo,
    int t)
{
    __shared__ __align__(16) float sA[BR][PAD];      // [row][k] within chunk
    __shared__ __align__(16) float sW[4 * BJ][PAD];  // [gate*16+jj][k] within chunk

    const int tid = threadIdx.x;
    const int jj  = tid & 15;        // local h-col
    const int rr  = tid >> 4;        // 0..15 -> rows rr and rr+16
    const int j0  = blockIdx.x * BJ;
    const int b0  = blockIdx.y * BR;

    const float* __restrict__ hin  = g_h[t & 1];
    float*       __restrict__ hout = g_h[(t + 1) & 1];

    u64 acc[2][4];
#pragma unroll
    for (int r = 0; r < 2; ++r)
#pragma unroll
        for (int g = 0; g < 4; ++g) acc[r][g] = 0ull;

    // W-loader mapping: thread -> (gate, k-within-chunk)
    const int gsel = tid >> 6;   // 0..3
    const int kkw  = tid & 63;   // 0..63
    const float* __restrict__ Wg = (gsel == 0) ? Wf : (gsel == 1) ? Wi : (gsel == 2) ? Wc : Wo;

    for (int ch = 0; ch < NCH; ++ch) {
        // ---- stage A chunk: rows = batch rows, cols = K chunk (x for k<256, h for k>=256)
#pragma unroll
        for (int it = 0; it < 2; ++it) {
            int idx4 = tid + it * 256;        // 512 float4's per chunk
            int r    = idx4 >> 4;             // 16 float4 per row
            int kk   = (idx4 & 15) * 4;
            int kg   = ch * KC + kk;
            const float* src = (kg < DIM)
                ? (x + ((size_t)t * BATCH + (b0 + r)) * DIM + kg)
                : (hin + (size_t)(b0 + r) * HID + (kg - DIM));
            float4 v = *(const float4*)src;
            float2* d = (float2*)&sA[r][kk];  // 8B aligned (kk mult of 4, pitch even)
            d[0] = make_float2(v.x, v.y);
            d[1] = make_float2(v.z, v.w);
        }
        // ---- stage W chunk: sW[g*16+jj][kk] = Wg[kglob][j0+jj]
        {
            int kg = ch * KC + kkw;
            const float4* p = (const float4*)(Wg + (size_t)kg * HID + j0);
#pragma unroll
            for (int m = 0; m < 4; ++m) {
                float4 v = p[m];
                sW[gsel * 16 + m * 4 + 0][kkw] = v.x;
                sW[gsel * 16 + m * 4 + 1][kkw] = v.y;
                sW[gsel * 16 + m * 4 + 2][kkw] = v.z;
                sW[gsel * 16 + m * 4 + 3][kkw] = v.w;
            }
        }
        __syncthreads();

        // ---- compute: 32 k-pairs, 8 ffma2 + 6 LDS.64 each
#pragma unroll 8
        for (int kp = 0; kp < KC / 2; ++kp) {
            u64 a0 = *(const u64*)&sA[rr][kp * 2];
            u64 a1 = *(const u64*)&sA[rr + 16][kp * 2];
#pragma unroll
            for (int g = 0; g < 4; ++g) {
                u64 w2 = *(const u64*)&sW[g * 16 + jj][kp * 2];
                acc[0][g] = ffma2(a0, w2, acc[0][g]);
                acc[1][g] = ffma2(a1, w2, acc[1][g]);
            }
        }
        __syncthreads();
    }

    // ---- epilogue: all 4 gates for (b, j) live in this thread's registers
    const int j = j0 + jj;
    const float bfv = bf[j], biv = bi[j], bcv = bc[j], bov = bo[j];
#pragma unroll
    for (int r = 0; r < 2; ++r) {
        const int b = b0 + rr + r * 16;
        float fpre = f2sum(acc[r][0]) + bfv;
        float ipre = f2sum(acc[r][1]) + biv;
        float cpre = f2sum(acc[r][2]) + bcv;
        float opre = f2sum(acc[r][3]) + bov;
        float fg = sigmoid_f(fpre);
        float ig = sigmoid_f(ipre);
        float og = sigmoid_f(opre);
        float cc = tanh_f(cpre);

        size_t off = (size_t)b * HID + j;
        float cold = g_c[off];
        float cnew = fg * cold + ig * cc;
        float hnew = og * tanh_f(cnew);
        bool active = t < lengths[b];
        g_c[off]  = active ? cnew : cold;
        hout[off] = active ? hnew : hin[off];
    }
}

// y = h @ Wy + by ; also emit h (outputs are (y, h) concatenated).
__global__ void lstm_final(const float* __restrict__ Wy,
                           const float* __restrict__ by,
                           float* __restrict__ out,
                           int out_size)
{
    __shared__ float hrow[HID];
    const int b   = blockIdx.x;
    const int tid = threadIdx.x;   // 64 threads = OUTD

    const float* __restrict__ hfin = g_h[T_STEPS & 1];  // buffer 0 after 512 steps
    for (int k = tid; k < HID; k += OUTD) hrow[k] = hfin[(size_t)b * HID + k];
    __syncthreads();

    float acc = by[tid];
#pragma unroll 8
    for (int k = 0; k < HID; ++k) acc += hrow[k] * Wy[(size_t)k * OUTD + tid];
    out[(size_t)b * OUTD + tid] = acc;

    if (out_size >= BATCH * OUTD + BATCH * HID) {
        for (int k = tid; k < HID; k += OUTD)
            out[BATCH * OUTD + (size_t)b * HID + k] = hrow[k];
    }
}

extern "C" void kernel_launch(void* const* d_in, const int* in_sizes, int n_in,
                              void* d_out, int out_size) {
    const float* x       = (const float*)d_in[0];
    const int*   lengths = (const int*)  d_in[1];
    const float* Wf      = (const float*)d_in[2];
    const float* bf      = (const float*)d_in[3];
    const float* Wi      = (const float*)d_in[4];
    const float* bi      = (const float*)d_in[5];
    const float* Wc      = (const float*)d_in[6];
    const float* bc      = (const float*)d_in[7];
    const float* Wo      = (const float*)d_in[8];
    const float* bo      = (const float*)d_in[9];
    const float* Wy      = (const float*)d_in[10];
    const float* by      = (const float*)d_in[11];
    float* out = (float*)d_out;

    zero_state<<<128, 512>>>();
    for (int t = 0; t < T_STEPS; ++t) {
        lstm_step<<<dim3(HID / BJ, BATCH / BR), 256>>>(
            x, lengths, Wf, bf, Wi, bi, Wc, bc, Wo, bo, t);
    }
    lstm_final<<<BATCH, OUTD>>>(Wy, by, out, out_size);
}

// round 3
// speedup vs baseline: 2.4195x; 2.4173x over previous
#include <cuda_runtime.h>

#define TS   512
#define BSZ  256
#define DIN  256
#define HID  256
#define OUTD 64
#define KTOT 512
#define NCTA 128
#define PA   520                 // sA pitch (floats): 520 % 32 == 8 -> conflict-free lane pattern
#define PW   68                  // sW pitch (floats): 68 % 32 == 4  -> conflict-free lane pattern
#define PR   68                  // sRed row pitch

#define SW_FLOATS (KTOT * PW)            // 34816
#define SREG_FLOATS (8 * 32 * PR)        // 17408  (>= 32*PA? no: sA needs 32*520=16640; region=max)
#define SA_REGION  (SREG_FLOATS)         // 17408 floats covers both sA (16640) and sRed (17408)
#define SMEM_BYTES ((SW_FLOATS + SA_REGION) * 4)   // 208,896 B

__device__ float    g_hbuf[2][BSZ * HID];
__device__ unsigned g_bar;

typedef unsigned long long u64;

__device__ __forceinline__ u64 ffma2(u64 a, u64 b, u64 c) {
    u64 d; asm("fma.rn.f32x2 %0, %1, %2, %3;" : "=l"(d) : "l"(a), "l"(b), "l"(c)); return d;
}
__device__ __forceinline__ u64 dup2(float a) {
    u64 d; asm("mov.b64 %0, {%1, %1};" : "=l"(d) : "f"(a)); return d;
}
__device__ __forceinline__ float sigmoidf_(float x) { return 1.0f / (1.0f + __expf(-x)); }
__device__ __forceinline__ float tanhf_(float x) {
    float e = __expf(2.0f * x);
    return 1.0f - 2.0f / (e + 1.0f);
}

__global__ void init_state() {
    int i = blockIdx.x * blockDim.x + threadIdx.x;
    if (i == 0) g_bar = 0u;
    if (i < BSZ * HID / 4) ((float4*)g_hbuf[0])[i] = make_float4(0.f, 0.f, 0.f, 0.f);
}

__global__ void __launch_bounds__(256, 1) lstm_persistent(
    const float* __restrict__ x, const int* __restrict__ lengths,
    const float* __restrict__ Wf, const float* __restrict__ bf,
    const float* __restrict__ Wi, const float* __restrict__ bi,
    const float* __restrict__ Wc, const float* __restrict__ bc,
    const float* __restrict__ Wo, const float* __restrict__ bo,
    const float* __restrict__ Wy, const float* __restrict__ by,
    float* __restrict__ out)
{
    extern __shared__ float sm[];
    float* sW   = sm;                 // [512][PW]  gate-interleaved W slice, persistent across steps
    float* sA   = sm + SW_FLOATS;     // [32][PA]   A = [x_t ; h] slice (per step)
    float* sRed = sA;                 // [8][32][PR] partial-sum buffer (aliases sA)

    const int tid  = threadIdx.x;
    const int w    = tid >> 5;
    const int lane = tid & 31;
    const int rthr = lane >> 3;       // 0..3  -> rows rthr + 4j
    const int cthr = lane & 7;        // 0..7  -> cols cthr*4..+3 and +32..+35
    const int bid  = blockIdx.x;
    const int ct   = bid & 15;
    const int rt   = bid >> 4;
    const int b0   = rt * 32;
    const int j0   = ct * 16;

    // ---- stage W slice into smem ONCE (persists for all 512 steps) ----
    {
        const int g  = tid >> 6;
        const int kk = tid & 63;
        const float* __restrict__ Wg = (g == 0) ? Wf : (g == 1) ? Wi : (g == 2) ? Wc : Wo;
        #pragma unroll
        for (int kb = 0; kb < 8; ++kb) {
            int k = kb * 64 + kk;
            const float4* src = (const float4*)(Wg + (size_t)k * HID + j0);
            float4* dst = (float4*)(sW + k * PW + g * 16);
            dst[0] = src[0]; dst[1] = src[1]; dst[2] = src[2]; dst[3] = src[3];
        }
    }

    // ---- epilogue-thread state: owns (row=erow, hcols j0+2hp, j0+2hp+1); c,h in registers ----
    const int erow = tid & 31;
    const int hp   = tid >> 5;
    const int jj   = hp * 2;
    const float2 bfv = *(const float2*)(bf + j0 + jj);
    const float2 biv = *(const float2*)(bi + j0 + jj);
    const float2 bcv = *(const float2*)(bc + j0 + jj);
    const float2 bov = *(const float2*)(bo + j0 + jj);
    const int len = lengths[b0 + erow];
    float2 creg = make_float2(0.f, 0.f);
    float2 hreg = make_float2(0.f, 0.f);

    const int arow  = tid >> 3;
    const int afc   = tid & 7;
    const int kbase = w * 64;

    for (int t = 0; t < TS; ++t) {
        const float* __restrict__ hprev = g_hbuf[t & 1];
        float*       __restrict__ hnext = g_hbuf[(t + 1) & 1];

        // ---- stage A = [x_t ; h] for rows b0..b0+31 ----
        {
            const float* xr = x + ((size_t)t * BSZ + b0 + arow) * DIN;
            const float* hr = hprev + (size_t)(b0 + arow) * HID;
            float* dst = sA + arow * PA;
            #pragma unroll
            for (int i = 0; i < 8; ++i) {
                int k = (afc + 8 * i) * 4;
                *(float4*)(dst + k) = *(const float4*)(xr + k);
            }
            #pragma unroll
            for (int i = 8; i < 16; ++i) {
                int k = (afc + 8 * i) * 4;
                *(float4*)(dst + k) = __ldcg((const float4*)(hr + (k - DIN)));
            }
        }
        __syncthreads();

        // ---- GEMM slice: warp w covers k in [kbase, kbase+64); thread tile 8 rows x 8 cols ----
        u64 acc[8][4];
        #pragma unroll
        for (int j = 0; j < 8; ++j) { acc[j][0] = 0; acc[j][1] = 0; acc[j][2] = 0; acc[j][3] = 0; }

        #pragma unroll 2
        for (int kb = 0; kb < 16; ++kb) {
            const int k = kbase + kb * 4;
            float4 a4[8];
            #pragma unroll
            for (int j = 0; j < 8; ++j)
                a4[j] = *(const float4*)(sA + (rthr + 4 * j) * PA + k);
            #pragma unroll
            for (int kk = 0; kk < 4; ++kk) {
                const float* wp = sW + (k + kk) * PW + cthr * 4;
                ulonglong2 w0 = *(const ulonglong2*)(wp);
                ulonglong2 w1 = *(const ulonglong2*)(wp + 32);
                #pragma unroll
                for (int j = 0; j < 8; ++j) {
                    float av = (kk == 0) ? a4[j].x : (kk == 1) ? a4[j].y : (kk == 2) ? a4[j].z : a4[j].w;
                    u64 ad = dup2(av);
                    acc[j][0] = ffma2(ad, w0.x, acc[j][0]);
                    acc[j][1] = ffma2(ad, w0.y, acc[j][1]);
                    acc[j][2] = ffma2(ad, w1.x, acc[j][2]);
                    acc[j][3] = ffma2(ad, w1.y, acc[j][3]);
                }
            }
        }
        __syncthreads();   // all reads of sA done before overwriting it as sRed

        // ---- store per-warp partials ----
        #pragma unroll
        for (int j = 0; j < 8; ++j) {
            const int row = rthr + 4 * j;
            float* base = sRed + (w * 32 + row) * PR + cthr * 4;
            ulonglong2 s0; s0.x = acc[j][0]; s0.y = acc[j][1];
            ulonglong2 s1; s1.x = acc[j][2]; s1.y = acc[j][3];
            *(ulonglong2*)(base)      = s0;
            *(ulonglong2*)(base + 32) = s1;
        }
        __syncthreads();

        // ---- epilogue: reduce 8 k-slices, activations, state update, publish h ----
        {
            float2 fs = make_float2(0.f, 0.f), is2 = fs, cs2 = fs, os2 = fs;
            #pragma unroll
            for (int ww = 0; ww < 8; ++ww) {
                const float* rb = sRed + (ww * 32 + erow) * PR + jj;
                float2 v;
                v = *(const float2*)(rb);        fs.x  += v.x; fs.y  += v.y;
                v = *(const float2*)(rb + 16);   is2.x += v.x; is2.y += v.y;
                v = *(const float2*)(rb + 32);   cs2.x += v.x; cs2.y += v.y;
                v = *(const float2*)(rb + 48);   os2.x += v.x; os2.y += v.y;
            }
            float f0 = sigmoidf_(fs.x  + bfv.x), f1 = sigmoidf_(fs.y  + bfv.y);
            float i0 = sigmoidf_(is2.x + biv.x), i1 = sigmoidf_(is2.y + biv.y);
            float o0 = sigmoidf_(os2.x + bov.x), o1 = sigmoidf_(os2.y + bov.y);
            float cc0 = tanhf_(cs2.x + bcv.x),   cc1 = tanhf_(cs2.y + bcv.y);
            float cn0 = f0 * creg.x + i0 * cc0;
            float cn1 = f1 * creg.y + i1 * cc1;
            float hn0 = o0 * tanhf_(cn0);
            float hn1 = o1 * tanhf_(cn1);
            if (t < len) { creg.x = cn0; creg.y = cn1; hreg.x = hn0; hreg.y = hn1; }
            *(float2*)(hnext + (size_t)(b0 + erow) * HID + j0 + jj) = hreg;
        }

        // ---- grid barrier ----
        __syncthreads();
        __threadfence();
        if (tid == 0) {
            atomicAdd(&g_bar, 1u);
            const unsigned tgt = (unsigned)(NCTA * (t + 1));
            unsigned v;
            do {
                asm volatile("ld.global.acquire.gpu.u32 %0, [%1];" : "=r"(v) : "l"(&g_bar));
                if (v >= tgt) break;
                __nanosleep(32);
            } while (true);
        }
        __syncthreads();
    }

    // ---- tail: y = h @ Wy + by, and copy h into the output ----
    const float* __restrict__ hfin = g_hbuf[0];   // step 511 wrote buffer (511+1)&1 == 0
    if (bid < 64) {
        const int row = bid * 4 + (tid >> 6);
        const int oc  = tid & 63;
        const float* hr = hfin + (size_t)row * HID;
        float acc = by[oc];
        #pragma unroll 4
        for (int k4 = 0; k4 < HID / 4; ++k4) {
            float4 hv = __ldcg((const float4*)(hr + k4 * 4));
            const float* wp = Wy + (size_t)k4 * 4 * OUTD + oc;
            acc += hv.x * wp[0] + hv.y * wp[OUTD] + hv.z * wp[2 * OUTD] + hv.w * wp[3 * OUTD];
        }
        out[(size_t)row * OUTD + oc] = acc;
    }
    {
        int idx = bid * 256 + tid;
        if (idx < BSZ * HID / 4) {
            float4 v = __ldcg(((const float4*)hfin) + idx);
            ((float4*)(out + BSZ * OUTD))[idx] = v;
        }
    }
}

extern "C" void kernel_launch(void* const* d_in, const int* in_sizes, int n_in,
                              void* d_out, int out_size) {
    const float* x       = (const float*)d_in[0];
    const int*   lengths = (const int*)  d_in[1];
    const float* Wf      = (const float*)d_in[2];
    const float* bf      = (const float*)d_in[3];
    const float* Wi      = (const float*)d_in[4];
    const float* bi      = (const float*)d_in[5];
    const float* Wc      = (const float*)d_in[6];
    const float* bc      = (const float*)d_in[7];
    const float* Wo      = (const float*)d_in[8];
    const float* bo      = (const float*)d_in[9];
    const float* Wy      = (const float*)d_in[10];
    const float* by      = (const float*)d_in[11];
    float* out = (float*)d_out;

    cudaFuncSetAttribute(lstm_persistent, cudaFuncAttributeMaxDynamicSharedMemorySize, SMEM_BYTES);

    init_state<<<64, 256>>>();
    lstm_persistent<<<NCTA, 256, SMEM_BYTES>>>(
        x, lengths, Wf, bf, Wi, bi, Wc, bc, Wo, bo, Wy, by, out);
}

// round 4
// speedup vs baseline: 2.4213x; 1.0007x over previous
#include <cuda_runtime.h>

#define TS   512
#define BSZ  256
#define DIN  256
#define HID  256
#define OUTD 64
#define KTOT 512
#define NCTA 128
#define PA   520                 // sA pitch (floats): 520 % 32 == 8 -> conflict-free lane pattern
#define PW   68                  // sW pitch (floats): 68 % 32 == 4  -> conflict-free lane pattern
#define PR   68                  // sRed row pitch

#define SW_FLOATS (KTOT * PW)            // 34816
#define SREG_FLOATS (8 * 32 * PR)        // 17408  (>= 32*PA? no: sA needs 32*520=16640; region=max)
#define SA_REGION  (SREG_FLOATS)         // 17408 floats covers both sA (16640) and sRed (17408)
#define SMEM_BYTES ((SW_FLOATS + SA_REGION) * 4)   // 208,896 B

__device__ float    g_hbuf[2][BSZ * HID];
__device__ unsigned g_bar;

typedef unsigned long long u64;

__device__ __forceinline__ u64 ffma2(u64 a, u64 b, u64 c) {
    u64 d; asm("fma.rn.f32x2 %0, %1, %2, %3;" : "=l"(d) : "l"(a), "l"(b), "l"(c)); return d;
}
__device__ __forceinline__ u64 dup2(float a) {
    u64 d; asm("mov.b64 %0, {%1, %1};" : "=l"(d) : "f"(a)); return d;
}
__device__ __forceinline__ float sigmoidf_(float x) { return 1.0f / (1.0f + __expf(-x)); }
__device__ __forceinline__ float tanhf_(float x) {
    float e = __expf(2.0f * x);
    return 1.0f - 2.0f / (e + 1.0f);
}

__global__ void init_state() {
    int i = blockIdx.x * blockDim.x + threadIdx.x;
    if (i == 0) g_bar = 0u;
    if (i < BSZ * HID / 4) ((float4*)g_hbuf[0])[i] = make_float4(0.f, 0.f, 0.f, 0.f);
}

__global__ void __launch_bounds__(256, 1) lstm_persistent(
    const float* __restrict__ x, const int* __restrict__ lengths,
    const float* __restrict__ Wf, const float* __restrict__ bf,
    const float* __restrict__ Wi, const float* __restrict__ bi,
    const float* __restrict__ Wc, const float* __restrict__ bc,
    const float* __restrict__ Wo, const float* __restrict__ bo,
    const float* __restrict__ Wy, const float* __restrict__ by,
    float* __restrict__ out)
{
    extern __shared__ float sm[];
    float* sW   = sm;                 // [512][PW]  gate-interleaved W slice, persistent across steps
    float* sA   = sm + SW_FLOATS;     // [32][PA]   A = [x_t ; h] slice (per step)
    float* sRed = sA;                 // [8][32][PR] partial-sum buffer (aliases sA)

    const int tid  = threadIdx.x;
    const int w    = tid >> 5;
    const int lane = tid & 31;
    const int rthr = lane >> 3;       // 0..3  -> rows rthr + 4j
    const int cthr = lane & 7;        // 0..7  -> cols cthr*4..+3 and +32..+35
    const int bid  = blockIdx.x;
    const int ct   = bid & 15;
    const int rt   = bid >> 4;
    const int b0   = rt * 32;
    const int j0   = ct * 16;

    // ---- stage W slice into smem ONCE (persists for all 512 steps) ----
    {
        const int g  = tid >> 6;
        const int kk = tid & 63;
        const float* __restrict__ Wg = (g == 0) ? Wf : (g == 1) ? Wi : (g == 2) ? Wc : Wo;
        #pragma unroll
        for (int kb = 0; kb < 8; ++kb) {
            int k = kb * 64 + kk;
            const float4* src = (const float4*)(Wg + (size_t)k * HID + j0);
            float4* dst = (float4*)(sW + k * PW + g * 16);
            dst[0] = src[0]; dst[1] = src[1]; dst[2] = src[2]; dst[3] = src[3];
        }
    }

    // ---- epilogue-thread state: owns (row=erow, hcols j0+2hp, j0+2hp+1); c,h in registers ----
    const int erow = tid & 31;
    const int hp   = tid >> 5;
    const int jj   = hp * 2;
    const float2 bfv = *(const float2*)(bf + j0 + jj);
    const float2 biv = *(const float2*)(bi + j0 + jj);
    const float2 bcv = *(const float2*)(bc + j0 + jj);
    const float2 bov = *(const float2*)(bo + j0 + jj);
    const int len = lengths[b0 + erow];
    float2 creg = make_float2(0.f, 0.f);
    float2 hreg = make_float2(0.f, 0.f);

    const int arow  = tid >> 3;
    const int afc   = tid & 7;
    const int kbase = w * 64;

    for (int t = 0; t < TS; ++t) {
        const float* __restrict__ hprev = g_hbuf[t & 1];
        float*       __restrict__ hnext = g_hbuf[(t + 1) & 1];

        // ---- stage A = [x_t ; h] for rows b0..b0+31 ----
        {
            const float* xr = x + ((size_t)t * BSZ + b0 + arow) * DIN;
            const float* hr = hprev + (size_t)(b0 + arow) * HID;
            float* dst = sA + arow * PA;
            #pragma unroll
            for (int i = 0; i < 8; ++i) {
                int k = (afc + 8 * i) * 4;
                *(float4*)(dst + k) = *(const float4*)(xr + k);
            }
            #pragma unroll
            for (int i = 8; i < 16; ++i) {
                int k = (afc + 8 * i) * 4;
                *(float4*)(dst + k) = __ldcg((const float4*)(hr + (k - DIN)));
            }
        }
        __syncthreads();

        // ---- GEMM slice: warp w covers k in [kbase, kbase+64); thread tile 8 rows x 8 cols ----
        u64 acc[8][4];
        #pragma unroll
        for (int j = 0; j < 8; ++j) { acc[j][0] = 0; acc[j][1] = 0; acc[j][2] = 0; acc[j][3] = 0; }

        #pragma unroll 2
        for (int kb = 0; kb < 16; ++kb) {
            const int k = kbase + kb * 4;
            float4 a4[8];
            #pragma unroll
            for (int j = 0; j < 8; ++j)
                a4[j] = *(const float4*)(sA + (rthr + 4 * j) * PA + k);
            #pragma unroll
            for (int kk = 0; kk < 4; ++kk) {
                const float* wp = sW + (k + kk) * PW + cthr * 4;
                ulonglong2 w0 = *(const ulonglong2*)(wp);
                ulonglong2 w1 = *(const ulonglong2*)(wp + 32);
                #pragma unroll
                for (int j = 0; j < 8; ++j) {
                    float av = (kk == 0) ? a4[j].x : (kk == 1) ? a4[j].y : (kk == 2) ? a4[j].z : a4[j].w;
                    u64 ad = dup2(av);
                    acc[j][0] = ffma2(ad, w0.x, acc[j][0]);
                    acc[j][1] = ffma2(ad, w0.y, acc[j][1]);
                    acc[j][2] = ffma2(ad, w1.x, acc[j][2]);
                    acc[j][3] = ffma2(ad, w1.y, acc[j][3]);
                }
            }
        }
        __syncthreads();   // all reads of sA done before overwriting it as sRed

        // ---- store per-warp partials ----
        #pragma unroll
        for (int j = 0; j < 8; ++j) {
            const int row = rthr + 4 * j;
            float* base = sRed + (w * 32 + row) * PR + cthr * 4;
            ulonglong2 s0; s0.x = acc[j][0]; s0.y = acc[j][1];
            ulonglong2 s1; s1.x = acc[j][2]; s1.y = acc[j][3];
            *(ulonglong2*)(base)      = s0;
            *(ulonglong2*)(base + 32) = s1;
        }
        __syncthreads();

        // ---- epilogue: reduce 8 k-slices, activations, state update, publish h ----
        {
            float2 fs = make_float2(0.f, 0.f), is2 = fs, cs2 = fs, os2 = fs;
            #pragma unroll
            for (int ww = 0; ww < 8; ++ww) {
                const float* rb = sRed + (ww * 32 + erow) * PR + jj;
                float2 v;
                v = *(const float2*)(rb);        fs.x  += v.x; fs.y  += v.y;
                v = *(const float2*)(rb + 16);   is2.x += v.x; is2.y += v.y;
                v = *(const float2*)(rb + 32);   cs2.x += v.x; cs2.y += v.y;
                v = *(const float2*)(rb + 48);   os2.x += v.x; os2.y += v.y;
            }
            float f0 = sigmoidf_(fs.x  + bfv.x), f1 = sigmoidf_(fs.y  + bfv.y);
            float i0 = sigmoidf_(is2.x + biv.x), i1 = sigmoidf_(is2.y + biv.y);
            float o0 = sigmoidf_(os2.x + bov.x), o1 = sigmoidf_(os2.y + bov.y);
            float cc0 = tanhf_(cs2.x + bcv.x),   cc1 = tanhf_(cs2.y + bcv.y);
            float cn0 = f0 * creg.x + i0 * cc0;
            float cn1 = f1 * creg.y + i1 * cc1;
            float hn0 = o0 * tanhf_(cn0);
            float hn1 = o1 * tanhf_(cn1);
            if (t < len) { creg.x = cn0; creg.y = cn1; hreg.x = hn0; hreg.y = hn1; }
            *(float2*)(hnext + (size_t)(b0 + erow) * HID + j0 + jj) = hreg;
        }

        // ---- grid barrier ----
        __syncthreads();
        __threadfence();
        if (tid == 0) {
            atomicAdd(&g_bar, 1u);
            const unsigned tgt = (unsigned)(NCTA * (t + 1));
            unsigned v;
            do {
                asm volatile("ld.global.acquire.gpu.u32 %0, [%1];" : "=r"(v) : "l"(&g_bar));
                if (v >= tgt) break;
                __nanosleep(32);
            } while (true);
        }
        __syncthreads();
    }

    // ---- tail: y = h @ Wy + by, and copy h into the output ----
    const float* __restrict__ hfin = g_hbuf[0];   // step 511 wrote buffer (511+1)&1 == 0
    if (bid < 64) {
        const int row = bid * 4 + (tid >> 6);
        const int oc  = tid & 63;
        const float* hr = hfin + (size_t)row * HID;
        float acc = by[oc];
        #pragma unroll 4
        for (int k4 = 0; k4 < HID / 4; ++k4) {
            float4 hv = __ldcg((const float4*)(hr + k4 * 4));
            const float* wp = Wy + (size_t)k4 * 4 * OUTD + oc;
            acc += hv.x * wp[0] + hv.y * wp[OUTD] + hv.z * wp[2 * OUTD] + hv.w * wp[3 * OUTD];
        }
        out[(size_t)row * OUTD + oc] = acc;
    }
    {
        int idx = bid * 256 + tid;
        if (idx < BSZ * HID / 4) {
            float4 v = __ldcg(((const float4*)hfin) + idx);
            ((float4*)(out + BSZ * OUTD))[idx] = v;
        }
    }
}

extern "C" void kernel_launch(void* const* d_in, const int* in_sizes, int n_in,
                              void* d_out, int out_size) {
    const float* x       = (const float*)d_in[0];
    const int*   lengths = (const int*)  d_in[1];
    const float* Wf      = (const float*)d_in[2];
    const float* bf      = (const float*)d_in[3];
    const float* Wi      = (const float*)d_in[4];
    const float* bi      = (const float*)d_in[5];
    const float* Wc      = (const float*)d_in[6];
    const float* bc      = (const float*)d_in[7];
    const float* Wo      = (const float*)d_in[8];
    const float* bo      = (const float*)d_in[9];
    const float* Wy      = (const float*)d_in[10];
    const float* by      = (const float*)d_in[11];
    float* out = (float*)d_out;

    cudaFuncSetAttribute(lstm_persistent, cudaFuncAttributeMaxDynamicSharedMemorySize, SMEM_BYTES);

    init_state<<<64, 256>>>();
    lstm_persistent<<<NCTA, 256, SMEM_BYTES>>>(
        x, lengths, Wf, bf, Wi, bi, Wc, bc, Wo, bo, Wy, by, out);
}

// round 7
// speedup vs baseline: 2.9118x; 1.2025x over previous
#include <cuda_runtime.h>
#include <cuda_bf16.h>
#include <cstdint>
#include <cstring>

#define TS   512
#define BSZ  256
#define DIN  256
#define HID  256
#define OUTD 64
#define MROWS (TS * BSZ)
#define NCTA 256
#define PA   264
#define PW   68
#define PR   68
#define PAK  40      // staged tile pitch in bf16 (80B rows: ldmatrix conflict-free)

// serial-kernel smem
#define SW_F   (256 * PW)
#define SREG_F (8 * 16 * PR)
#define SMEM_SERIAL ((SW_F + SREG_F) * 4)      // 104448 B

// xw_mma smem layout (bytes)
#define OFF_BIAS 0
#define OFF_AH   1024
#define OFF_AL   (OFF_AH + 128 * PAK * 2)      // +10240
#define OFF_BH   (OFF_AL + 128 * PAK * 2)
#define OFF_BL   (OFF_BH + 128 * PAK * 2)
#define SMEM_MMA (OFF_BL + 128 * PAK * 2)      // 41984 B

extern __shared__ char smem_dyn[];

__device__ float          g_xwb[(size_t)MROWS * 1024];   // x@Wx + b, [m][g*256+j]
__device__ __nv_bfloat16  g_ah[(size_t)MROWS * DIN];
__device__ __nv_bfloat16  g_al[(size_t)MROWS * DIN];
__device__ __nv_bfloat16  g_wth[1024 * 256];              // W^T hi [n][k]
__device__ __nv_bfloat16  g_wtl[1024 * 256];              // W^T lo
__device__ float          g_hbuf[2][BSZ * HID];
__device__ unsigned       g_bar;

typedef unsigned long long u64;

__device__ __forceinline__ u64 ffma2(u64 a, u64 b, u64 c) {
    u64 d; asm("fma.rn.f32x2 %0, %1, %2, %3;" : "=l"(d) : "l"(a), "l"(b), "l"(c)); return d;
}
__device__ __forceinline__ u64 dup2(float a) {
    u64 d; asm("mov.b64 %0, {%1, %1};" : "=l"(d) : "f"(a)); return d;
}
__device__ __forceinline__ float sigmoidf_(float x) { return 1.0f / (1.0f + __expf(-x)); }
__device__ __forceinline__ float tanhf_(float x) {
    float e = __expf(2.0f * x); return 1.0f - 2.0f / (e + 1.0f);
}
__device__ __forceinline__ uint32_t s2u(const void* p) {
    uint32_t a; asm("{ .reg .u64 t; cvta.to.shared.u64 t, %1; cvt.u32.u64 %0, t; }" : "=r"(a) : "l"(p));
    return a;
}
__device__ __forceinline__ uint32_t pack2(float a, float b) {
    __nv_bfloat162 t; t.x = __float2bfloat16(a); t.y = __float2bfloat16(b);
    uint32_t r; memcpy(&r, &t, 4); return r;
}

#define LDSM4(d0, d1, d2, d3, addr) \
    asm volatile("ldmatrix.sync.aligned.m8n8.x4.shared.b16 {%0,%1,%2,%3}, [%4];" \
                 : "=r"(d0), "=r"(d1), "=r"(d2), "=r"(d3) : "r"(addr))

#define MMA16816(c, a, b0, b1) \
    asm volatile("mma.sync.aligned.m16n8k16.row.col.f32.bf16.bf16.f32 " \
                 "{%0,%1,%2,%3}, {%4,%5,%6,%7}, {%8,%9}, {%0,%1,%2,%3};" \
                 : "+f"((c)[0]), "+f"((c)[1]), "+f"((c)[2]), "+f"((c)[3]) \
                 : "r"((a)[0]), "r"((a)[1]), "r"((a)[2]), "r"((a)[3]), "r"(b0), "r"(b1))

// ---------------- conversions ----------------
__global__ void convert_x(const float* __restrict__ x) {
    size_t i = (size_t)blockIdx.x * 256 + threadIdx.x;   // over MROWS*DIN/4 float4
    float4 v = ((const float4*)x)[i];
    float h0 = __bfloat162float(__float2bfloat16(v.x));
    float h1 = __bfloat162float(__float2bfloat16(v.y));
    float h2 = __bfloat162float(__float2bfloat16(v.z));
    float h3 = __bfloat162float(__float2bfloat16(v.w));
    uint2 ph, pl;
    ph.x = pack2(v.x, v.y); ph.y = pack2(v.z, v.w);
    pl.x = pack2(v.x - h0, v.y - h1); pl.y = pack2(v.z - h2, v.w - h3);
    ((uint2*)g_ah)[i] = ph;
    ((uint2*)g_al)[i] = pl;
}

__global__ void convert_w(const float* __restrict__ Wf, const float* __restrict__ Wi,
                          const float* __restrict__ Wc, const float* __restrict__ Wo) {
    int n = blockIdx.x, k = threadIdx.x;
    int g = n >> 8, j = n & 255;
    const float* Wg = (g == 0) ? Wf : (g == 1) ? Wi : (g == 2) ? Wc : Wo;
    float v = Wg[(size_t)k * HID + j];            // x-part rows (k < 256)
    float h = __bfloat162float(__float2bfloat16(v));
    g_wth[n * 256 + k] = __float2bfloat16(v);
    g_wtl[n * 256 + k] = __float2bfloat16(v - h);
}

// ---------------- xwb = x @ Wx + b via mma.sync bf16 3-term split ----------------
__global__ void __launch_bounds__(256) xw_mma(
    const float* __restrict__ bfp, const float* __restrict__ bip,
    const float* __restrict__ bcp, const float* __restrict__ bop)
{
    char* sm = smem_dyn;
    float* sBias = (float*)(sm + OFF_BIAS);
    const uint32_t uAh = s2u(sm + OFF_AH);
    const uint32_t uAl = s2u(sm + OFF_AL);
    const uint32_t uBh = s2u(sm + OFF_BH);
    const uint32_t uBl = s2u(sm + OFF_BL);

    const int tid  = threadIdx.x;
    const int w    = tid >> 5;
    const int lane = tid & 31;
    const int wm   = w & 3;           // m-block (32 rows each)
    const int wn   = w >> 2;          // n-block (64 cols each)
    const int n0   = blockIdx.x * 128;
    const int m0   = blockIdx.y * 128;

    if (tid < 128) {
        int g = n0 >> 8;
        const float* bg = (g == 0) ? bfp : (g == 1) ? bip : (g == 2) ? bcp : bop;
        sBias[tid] = bg[(n0 & 255) + tid];
    }

    // ldmatrix lane address components
    const int arow  = lane & 15;                       // A: rows 0..15
    const int ahalf = (lane >> 4) & 1;                 // A: k-half
    const int brow  = ((lane >> 4) & 1) * 8 + (lane & 7);  // B: n-row in 16-row pair
    const int bcol  = ((lane >> 3) & 1) * 8;           // B: k-half

    float c[2][8][4];
    #pragma unroll
    for (int mt = 0; mt < 2; ++mt)
        #pragma unroll
        for (int nt = 0; nt < 8; ++nt)
            #pragma unroll
            for (int q = 0; q < 4; ++q) c[mt][nt][q] = 0.f;

    for (int ck = 0; ck < 8; ++ck) {
        const int k0 = ck * 32;
        __syncthreads();
        // stage 4 matrices: 128 rows x 32 bf16 each, pitch PAK
        #pragma unroll
        for (int it = 0; it < 2; ++it) {
            int idx = tid + it * 256;
            int r = idx >> 2, cq = idx & 3;
            uint32_t doff = (uint32_t)(r * (PAK * 2) + cq * 16);
            *(uint4*)(sm + OFF_AH + doff) = *(const uint4*)(g_ah  + (size_t)(m0 + r) * 256 + k0 + cq * 8);
            *(uint4*)(sm + OFF_AL + doff) = *(const uint4*)(g_al  + (size_t)(m0 + r) * 256 + k0 + cq * 8);
            *(uint4*)(sm + OFF_BH + doff) = *(const uint4*)(g_wth + (size_t)(n0 + r) * 256 + k0 + cq * 8);
            *(uint4*)(sm + OFF_BL + doff) = *(const uint4*)(g_wtl + (size_t)(n0 + r) * 256 + k0 + cq * 8);
        }
        __syncthreads();

        #pragma unroll
        for (int ks = 0; ks < 2; ++ks) {
            const int kk = ks * 16;
            uint32_t ah[2][4], al[2][4];
            #pragma unroll
            for (int mt = 0; mt < 2; ++mt) {
                uint32_t ao = (uint32_t)((wm * 32 + mt * 16 + arow) * (PAK * 2) + (kk + ahalf * 8) * 2);
                LDSM4(ah[mt][0], ah[mt][1], ah[mt][2], ah[mt][3], uAh + ao);
                LDSM4(al[mt][0], al[mt][1], al[mt][2], al[mt][3], uAl + ao);
            }
            #pragma unroll
            for (int np = 0; np < 4; ++np) {       // n-pair: n-tiles 2np, 2np+1
                uint32_t bo = (uint32_t)((wn * 64 + np * 16 + brow) * (PAK * 2) + (kk + bcol) * 2);
                uint32_t bh[4], bl[4];
                LDSM4(bh[0], bh[1], bh[2], bh[3], uBh + bo);
                LDSM4(bl[0], bl[1], bl[2], bl[3], uBl + bo);
                #pragma unroll
                for (int mt = 0; mt < 2; ++mt) {
                    MMA16816(c[mt][2 * np],     ah[mt], bh[0], bh[1]);
                    MMA16816(c[mt][2 * np + 1], ah[mt], bh[2], bh[3]);
                    MMA16816(c[mt][2 * np],     ah[mt], bl[0], bl[1]);
                    MMA16816(c[mt][2 * np + 1], ah[mt], bl[2], bl[3]);
                    MMA16816(c[mt][2 * np],     al[mt], bh[0], bh[1]);
                    MMA16816(c[mt][2 * np + 1], al[mt], bh[2], bh[3]);
                }
            }
        }
    }

    // epilogue: D rows (g, g+8) cols 2*tg within each m16n8 tile; +bias; direct STG.64
    const int g  = lane >> 2;
    const int tg = lane & 3;
    float* base = g_xwb + (size_t)(m0 + wm * 32) * 1024 + n0 + wn * 64;
    #pragma unroll
    for (int mt = 0; mt < 2; ++mt) {
        #pragma unroll
        for (int nt = 0; nt < 8; ++nt) {
            float2 bv = *(float2*)&sBias[wn * 64 + nt * 8 + 2 * tg];
            float2 v0, v1;
            v0.x = c[mt][nt][0] + bv.x; v0.y = c[mt][nt][1] + bv.y;
            v1.x = c[mt][nt][2] + bv.x; v1.y = c[mt][nt][3] + bv.y;
            *(float2*)(base + (size_t)(mt * 16 + g)     * 1024 + nt * 8 + 2 * tg) = v0;
            *(float2*)(base + (size_t)(mt * 16 + g + 8) * 1024 + nt * 8 + 2 * tg) = v1;
        }
    }
}

// ---------------- init ----------------
__global__ void init_state() {
    int i = blockIdx.x * blockDim.x + threadIdx.x;
    if (i == 0) g_bar = 0u;
    if (i < BSZ * HID / 4) ((float4*)g_hbuf[0])[i] = make_float4(0.f, 0.f, 0.f, 0.f);
}

// ---------------- serial loop: h @ Wh only (K=256) ----------------
__global__ void __launch_bounds__(256, 2) lstm_serial(
    const int* __restrict__ lengths,
    const float* __restrict__ Wf, const float* __restrict__ Wi,
    const float* __restrict__ Wc, const float* __restrict__ Wo,
    const float* __restrict__ Wy, const float* __restrict__ by,
    float* __restrict__ out)
{
    float* sm = (float*)smem_dyn;
    float* sW   = sm;                 // [256][PW]
    float* sA   = sm + SW_F;          // [16][PA]
    float* sRed = sA;                 // [8][16][PR] aliased

    const int tid  = threadIdx.x;
    const int w    = tid >> 5;
    const int lane = tid & 31;
    const int rthr = lane >> 3;
    const int cthr = lane & 7;
    const int bid  = blockIdx.x;
    const int b0   = (bid >> 4) * 16;
    const int j0   = (bid & 15) * 16;

    // stage Wh slice once (rows DIN..DIN+255)
    {
        const int g = tid >> 6, kk = tid & 63;
        const float* __restrict__ Wg = (g == 0) ? Wf : (g == 1) ? Wi : (g == 2) ? Wc : Wo;
        #pragma unroll
        for (int kb = 0; kb < 4; ++kb) {
            int k = kb * 64 + kk;
            const float4* src = (const float4*)(Wg + (size_t)(DIN + k) * HID + j0);
            float4* dst = (float4*)(sW + k * PW + g * 16);
            dst[0] = src[0]; dst[1] = src[1]; dst[2] = src[2]; dst[3] = src[3];
        }
    }

    const int erow = tid >> 4;
    const int jj   = tid & 15;
    const int len  = lengths[b0 + erow];
    float creg = 0.f, hreg = 0.f;
    const int kbase = w * 32;

    for (int t = 0; t < TS; ++t) {
        const float* __restrict__ hprev = g_hbuf[t & 1];
        float*       __restrict__ hnext = g_hbuf[(t + 1) & 1];

        const float* xrow = g_xwb + ((size_t)t * BSZ + b0 + erow) * 1024 + j0 + jj;
        float pf = __ldcg(xrow), pi = __ldcg(xrow + 256);
        float pc = __ldcg(xrow + 512), po = __ldcg(xrow + 768);

        #pragma unroll
        for (int it = 0; it < 4; ++it) {
            int idx = tid + it * 256;
            int r = idx >> 6, cc = idx & 63;
            float4 v = __ldcg((const float4*)(hprev + (size_t)(b0 + r) * HID + cc * 4));
            *(float4*)(sA + r * PA + cc * 4) = v;
        }
        __syncthreads();

        u64 acc[4][4];
        #pragma unroll
        for (int j = 0; j < 4; ++j) { acc[j][0] = 0; acc[j][1] = 0; acc[j][2] = 0; acc[j][3] = 0; }
        #pragma unroll
        for (int kb = 0; kb < 8; ++kb) {
            const int k = kbase + kb * 4;
            float4 a4[4];
            #pragma unroll
            for (int j = 0; j < 4; ++j)
                a4[j] = *(const float4*)(sA + (rthr + 4 * j) * PA + k);
            #pragma unroll
            for (int kk = 0; kk < 4; ++kk) {
                const float* wp = sW + (k + kk) * PW + cthr * 4;
                ulonglong2 w0 = *(const ulonglong2*)(wp);
                ulonglong2 w1 = *(const ulonglong2*)(wp + 32);
                #pragma unroll
                for (int j = 0; j < 4; ++j) {
                    float av = (kk == 0) ? a4[j].x : (kk == 1) ? a4[j].y : (kk == 2) ? a4[j].z : a4[j].w;
                    u64 ad = dup2(av);
                    acc[j][0] = ffma2(ad, w0.x, acc[j][0]);
                    acc[j][1] = ffma2(ad, w0.y, acc[j][1]);
                    acc[j][2] = ffma2(ad, w1.x, acc[j][2]);
                    acc[j][3] = ffma2(ad, w1.y, acc[j][3]);
                }
            }
        }
        __syncthreads();

        #pragma unroll
        for (int j = 0; j < 4; ++j) {
            float* base = sRed + (w * 16 + rthr + 4 * j) * PR + cthr * 4;
            ulonglong2 s0; s0.x = acc[j][0]; s0.y = acc[j][1];
            ulonglong2 s1; s1.x = acc[j][2]; s1.y = acc[j][3];
            *(ulonglong2*)(base)      = s0;
            *(ulonglong2*)(base + 32) = s1;
        }
        __syncthreads();

        {
            float fs = pf, is2 = pi, cs2 = pc, os2 = po;
            #pragma unroll
            for (int ww = 0; ww < 8; ++ww) {
                const float* rb = sRed + (ww * 16 + erow) * PR + jj;
                fs  += rb[0];
                is2 += rb[16];
                cs2 += rb[32];
                os2 += rb[48];
            }
            float fg = sigmoidf_(fs), ig = sigmoidf_(is2), og = sigmoidf_(os2);
            float cc = tanhf_(cs2);
            float cn = fg * creg + ig * cc;
            float hn = og * tanhf_(cn);
            if (t < len) { creg = cn; hreg = hn; }
            hnext[(size_t)(b0 + erow) * HID + j0 + jj] = hreg;
        }

        __syncthreads();
        __threadfence();
        if (tid == 0) {
            atomicAdd(&g_bar, 1u);
            const unsigned tgt = (unsigned)(NCTA * (t + 1));
            unsigned v;
            do {
                asm volatile("ld.global.acquire.gpu.u32 %0, [%1];" : "=r"(v) : "l"(&g_bar));
                if (v >= tgt) break;
                __nanosleep(32);
            } while (true);
        }
        __syncthreads();
    }

    // tail: y = h @ Wy + by, then copy h
    const float* __restrict__ hfin = g_hbuf[0];
    if (bid < 64) {
        const int row = bid * 4 + (tid >> 6);
        const int oc  = tid & 63;
        const float* hr = hfin + (size_t)row * HID;
        float acc = by[oc];
        #pragma unroll 4
        for (int k4 = 0; k4 < HID / 4; ++k4) {
            float4 hv = __ldcg((const float4*)(hr + k4 * 4));
            const float* wp = Wy + (size_t)k4 * 4 * OUTD + oc;
            acc += hv.x * wp[0] + hv.y * wp[OUTD] + hv.z * wp[2 * OUTD] + hv.w * wp[3 * OUTD];
        }
        out[(size_t)row * OUTD + oc] = acc;
    }
    {
        int idx = bid * 256 + tid;
        if (idx < BSZ * HID / 4) {
            float4 v = __ldcg(((const float4*)hfin) + idx);
            ((float4*)(out + BSZ * OUTD))[idx] = v;
        }
    }
}

extern "C" void kernel_launch(void* const* d_in, const int* in_sizes, int n_in,
                              void* d_out, int out_size) {
    const float* x       = (const float*)d_in[0];
    const int*   lengths = (const int*)  d_in[1];
    const float* Wf = (const float*)d_in[2];  const float* bf = (const float*)d_in[3];
    const float* Wi = (const float*)d_in[4];  const float* bi = (const float*)d_in[5];
    const float* Wc = (const float*)d_in[6];  const float* bc = (const float*)d_in[7];
    const float* Wo = (const float*)d_in[8];  const float* bo = (const float*)d_in[9];
    const float* Wy = (const float*)d_in[10]; const float* by = (const float*)d_in[11];
    float* out = (float*)d_out;

    cudaFuncSetAttribute(xw_mma, cudaFuncAttributeMaxDynamicSharedMemorySize, SMEM_MMA);
    cudaFuncSetAttribute(lstm_serial, cudaFuncAttributeMaxDynamicSharedMemorySize, SMEM_SERIAL);

    convert_x<<<(MROWS * DIN / 4) / 256, 256>>>(x);
    convert_w<<<1024, 256>>>(Wf, Wi, Wc, Wo);
    xw_mma<<<dim3(8, MROWS / 128), 256, SMEM_MMA>>>(bf, bi, bc, bo);
    init_state<<<64, 256>>>();
    lstm_serial<<<NCTA, 256, SMEM_SERIAL>>>(lengths, Wf, Wi, Wc, Wo, Wy, by, out);
}

// round 8
// speedup vs baseline: 3.1075x; 1.0672x over previous
#include <cuda_runtime.h>
#include <cuda_bf16.h>
#include <cstdint>
#include <cstring>

#define TS   512
#define BSZ  256
#define DIN  256
#define HID  256
#define OUTD 64
#define MROWS (TS * BSZ)
#define NCTA 256
#define PA   264
#define PW   68
#define PR   68
#define PAK  40      // staged tile pitch in bf16 (80B rows: ldmatrix conflict-free)

// serial-kernel smem
#define SW_F   (256 * PW)
#define SREG_F (8 * 16 * PR)
#define SMEM_SERIAL ((SW_F + SREG_F) * 4)      // 104448 B

// xw_mma smem layout (bytes)
#define OFF_BIAS 0
#define OFF_AH   1024
#define OFF_AL   (OFF_AH + 128 * PAK * 2)
#define OFF_BH   (OFF_AL + 128 * PAK * 2)
#define OFF_BL   (OFF_BH + 128 * PAK * 2)
#define SMEM_MMA (OFF_BL + 128 * PAK * 2)      // 41984 B

extern __shared__ char smem_dyn[];

__device__ float          g_xwb[(size_t)MROWS * 1024];   // x@Wx + b, [m][g*256+j]
__device__ __nv_bfloat16  g_ah[(size_t)MROWS * DIN];
__device__ __nv_bfloat16  g_al[(size_t)MROWS * DIN];
__device__ __nv_bfloat16  g_wth[1024 * 256];              // W^T hi [n][k]
__device__ __nv_bfloat16  g_wtl[1024 * 256];              // W^T lo
__device__ float          g_hbuf[2][BSZ * HID];
__device__ unsigned       g_rbar[16][64];                 // per-row-group barriers (256B apart)
__device__ unsigned       g_bar;                          // final global barrier

typedef unsigned long long u64;

__device__ __forceinline__ u64 ffma2(u64 a, u64 b, u64 c) {
    u64 d; asm("fma.rn.f32x2 %0, %1, %2, %3;" : "=l"(d) : "l"(a), "l"(b), "l"(c)); return d;
}
__device__ __forceinline__ u64 dup2(float a) {
    u64 d; asm("mov.b64 %0, {%1, %1};" : "=l"(d) : "f"(a)); return d;
}
__device__ __forceinline__ float sigmoidf_(float x) { return 1.0f / (1.0f + __expf(-x)); }
__device__ __forceinline__ float tanhf_(float x) {
    float e = __expf(2.0f * x); return 1.0f - 2.0f / (e + 1.0f);
}
__device__ __forceinline__ uint32_t s2u(const void* p) {
    uint32_t a; asm("{ .reg .u64 t; cvta.to.shared.u64 t, %1; cvt.u32.u64 %0, t; }" : "=r"(a) : "l"(p));
    return a;
}
__device__ __forceinline__ uint32_t pack2(float a, float b) {
    __nv_bfloat162 t; t.x = __float2bfloat16(a); t.y = __float2bfloat16(b);
    uint32_t r; memcpy(&r, &t, 4); return r;
}
// release-arrive + acquire-poll barrier primitives (no membar.gl -> no CCTL.IVALL)
__device__ __forceinline__ void arrive_release(unsigned* ctr) {
    asm volatile("red.release.gpu.global.add.u32 [%0], %1;" :: "l"(ctr), "r"(1u) : "memory");
}
__device__ __forceinline__ void wait_target(const unsigned* ctr, unsigned tgt) {
    unsigned v;
    do {
        asm volatile("ld.global.acquire.gpu.u32 %0, [%1];" : "=r"(v) : "l"(ctr));
        if (v >= tgt) break;
        __nanosleep(20);
    } while (true);
}

#define LDSM4(d0, d1, d2, d3, addr) \
    asm volatile("ldmatrix.sync.aligned.m8n8.x4.shared.b16 {%0,%1,%2,%3}, [%4];" \
                 : "=r"(d0), "=r"(d1), "=r"(d2), "=r"(d3) : "r"(addr))

#define MMA16816(c, a, b0, b1) \
    asm volatile("mma.sync.aligned.m16n8k16.row.col.f32.bf16.bf16.f32 " \
                 "{%0,%1,%2,%3}, {%4,%5,%6,%7}, {%8,%9}, {%0,%1,%2,%3};" \
                 : "+f"((c)[0]), "+f"((c)[1]), "+f"((c)[2]), "+f"((c)[3]) \
                 : "r"((a)[0]), "r"((a)[1]), "r"((a)[2]), "r"((a)[3]), "r"(b0), "r"(b1))

// ---------------- conversions ----------------
__global__ void convert_x(const float* __restrict__ x) {
    size_t i = (size_t)blockIdx.x * 256 + threadIdx.x;
    float4 v = ((const float4*)x)[i];
    float h0 = __bfloat162float(__float2bfloat16(v.x));
    float h1 = __bfloat162float(__float2bfloat16(v.y));
    float h2 = __bfloat162float(__float2bfloat16(v.z));
    float h3 = __bfloat162float(__float2bfloat16(v.w));
    uint2 ph, pl;
    ph.x = pack2(v.x, v.y); ph.y = pack2(v.z, v.w);
    pl.x = pack2(v.x - h0, v.y - h1); pl.y = pack2(v.z - h2, v.w - h3);
    ((uint2*)g_ah)[i] = ph;
    ((uint2*)g_al)[i] = pl;
}

__global__ void convert_w(const float* __restrict__ Wf, const float* __restrict__ Wi,
                          const float* __restrict__ Wc, const float* __restrict__ Wo) {
    int n = blockIdx.x, k = threadIdx.x;
    int g = n >> 8, j = n & 255;
    const float* Wg = (g == 0) ? Wf : (g == 1) ? Wi : (g == 2) ? Wc : Wo;
    float v = Wg[(size_t)k * HID + j];
    float h = __bfloat162float(__float2bfloat16(v));
    g_wth[n * 256 + k] = __float2bfloat16(v);
    g_wtl[n * 256 + k] = __float2bfloat16(v - h);
}

// ---------------- xwb = x @ Wx + b via mma.sync bf16 3-term split ----------------
__global__ void __launch_bounds__(256) xw_mma(
    const float* __restrict__ bfp, const float* __restrict__ bip,
    const float* __restrict__ bcp, const float* __restrict__ bop)
{
    char* sm = smem_dyn;
    float* sBias = (float*)(sm + OFF_BIAS);
    const uint32_t uAh = s2u(sm + OFF_AH);
    const uint32_t uAl = s2u(sm + OFF_AL);
    const uint32_t uBh = s2u(sm + OFF_BH);
    const uint32_t uBl = s2u(sm + OFF_BL);

    const int tid  = threadIdx.x;
    const int w    = tid >> 5;
    const int lane = tid & 31;
    const int wm   = w & 3;
    const int wn   = w >> 2;
    const int n0   = blockIdx.x * 128;
    const int m0   = blockIdx.y * 128;

    if (tid < 128) {
        int g = n0 >> 8;
        const float* bg = (g == 0) ? bfp : (g == 1) ? bip : (g == 2) ? bcp : bop;
        sBias[tid] = bg[(n0 & 255) + tid];
    }

    const int arow  = lane & 15;
    const int ahalf = (lane >> 4) & 1;
    const int brow  = ((lane >> 4) & 1) * 8 + (lane & 7);
    const int bcol  = ((lane >> 3) & 1) * 8;

    float c[2][8][4];
    #pragma unroll
    for (int mt = 0; mt < 2; ++mt)
        #pragma unroll
        for (int nt = 0; nt < 8; ++nt)
            #pragma unroll
            for (int q = 0; q < 4; ++q) c[mt][nt][q] = 0.f;

    for (int ck = 0; ck < 8; ++ck) {
        const int k0 = ck * 32;
        __syncthreads();
        #pragma unroll
        for (int it = 0; it < 2; ++it) {
            int idx = tid + it * 256;
            int r = idx >> 2, cq = idx & 3;
            uint32_t doff = (uint32_t)(r * (PAK * 2) + cq * 16);
            *(uint4*)(sm + OFF_AH + doff) = *(const uint4*)(g_ah  + (size_t)(m0 + r) * 256 + k0 + cq * 8);
            *(uint4*)(sm + OFF_AL + doff) = *(const uint4*)(g_al  + (size_t)(m0 + r) * 256 + k0 + cq * 8);
            *(uint4*)(sm + OFF_BH + doff) = *(const uint4*)(g_wth + (size_t)(n0 + r) * 256 + k0 + cq * 8);
            *(uint4*)(sm + OFF_BL + doff) = *(const uint4*)(g_wtl + (size_t)(n0 + r) * 256 + k0 + cq * 8);
        }
        __syncthreads();

        #pragma unroll
        for (int ks = 0; ks < 2; ++ks) {
            const int kk = ks * 16;
            uint32_t ah[2][4], al[2][4];
            #pragma unroll
            for (int mt = 0; mt < 2; ++mt) {
                uint32_t ao = (uint32_t)((wm * 32 + mt * 16 + arow) * (PAK * 2) + (kk + ahalf * 8) * 2);
                LDSM4(ah[mt][0], ah[mt][1], ah[mt][2], ah[mt][3], uAh + ao);
                LDSM4(al[mt][0], al[mt][1], al[mt][2], al[mt][3], uAl + ao);
            }
            #pragma unroll
            for (int np = 0; np < 4; ++np) {
                uint32_t bo = (uint32_t)((wn * 64 + np * 16 + brow) * (PAK * 2) + (kk + bcol) * 2);
                uint32_t bh[4], bl[4];
                LDSM4(bh[0], bh[1], bh[2], bh[3], uBh + bo);
                LDSM4(bl[0], bl[1], bl[2], bl[3], uBl + bo);
                #pragma unroll
                for (int mt = 0; mt < 2; ++mt) {
                    MMA16816(c[mt][2 * np],     ah[mt], bh[0], bh[1]);
                    MMA16816(c[mt][2 * np + 1], ah[mt], bh[2], bh[3]);
                    MMA16816(c[mt][2 * np],     ah[mt], bl[0], bl[1]);
                    MMA16816(c[mt][2 * np + 1], ah[mt], bl[2], bl[3]);
                    MMA16816(c[mt][2 * np],     al[mt], bh[0], bh[1]);
                    MMA16816(c[mt][2 * np + 1], al[mt], bh[2], bh[3]);
                }
            }
        }
    }

    const int g  = lane >> 2;
    const int tg = lane & 3;
    float* base = g_xwb + (size_t)(m0 + wm * 32) * 1024 + n0 + wn * 64;
    #pragma unroll
    for (int mt = 0; mt < 2; ++mt) {
        #pragma unroll
        for (int nt = 0; nt < 8; ++nt) {
            float2 bv = *(float2*)&sBias[wn * 64 + nt * 8 + 2 * tg];
            float2 v0, v1;
            v0.x = c[mt][nt][0] + bv.x; v0.y = c[mt][nt][1] + bv.y;
            v1.x = c[mt][nt][2] + bv.x; v1.y = c[mt][nt][3] + bv.y;
            *(float2*)(base + (size_t)(mt * 16 + g)     * 1024 + nt * 8 + 2 * tg) = v0;
            *(float2*)(base + (size_t)(mt * 16 + g + 8) * 1024 + nt * 8 + 2 * tg) = v1;
        }
    }
}

// ---------------- init ----------------
__global__ void init_state() {
    int i = blockIdx.x * blockDim.x + threadIdx.x;
    if (i == 0) g_bar = 0u;
    if (i < 16 * 64) ((unsigned*)g_rbar)[i] = 0u;
    if (i < BSZ * HID / 4) ((float4*)g_hbuf[0])[i] = make_float4(0.f, 0.f, 0.f, 0.f);
}

// ---------------- serial loop: h @ Wh only (K=256) ----------------
__global__ void __launch_bounds__(256, 2) lstm_serial(
    const int* __restrict__ lengths,
    const float* __restrict__ Wf, const float* __restrict__ Wi,
    const float* __restrict__ Wc, const float* __restrict__ Wo,
    const float* __restrict__ Wy, const float* __restrict__ by,
    float* __restrict__ out)
{
    float* sm = (float*)smem_dyn;
    float* sW   = sm;                 // [256][PW]
    float* sA   = sm + SW_F;          // [16][PA]
    float* sRed = sA;                 // [8][16][PR] aliased

    const int tid  = threadIdx.x;
    const int w    = tid >> 5;
    const int lane = tid & 31;
    const int rthr = lane >> 3;
    const int cthr = lane & 7;
    const int bid  = blockIdx.x;
    const int rt   = bid >> 4;        // row group: 16 CTAs share rows b0..b0+15
    const int b0   = rt * 16;
    const int j0   = (bid & 15) * 16;
    unsigned* myctr = &g_rbar[rt][0];

    // stage Wh slice once (rows DIN..DIN+255)
    {
        const int g = tid >> 6, kk = tid & 63;
        const float* __restrict__ Wg = (g == 0) ? Wf : (g == 1) ? Wi : (g == 2) ? Wc : Wo;
        #pragma unroll
        for (int kb = 0; kb < 4; ++kb) {
            int k = kb * 64 + kk;
            const float4* src = (const float4*)(Wg + (size_t)(DIN + k) * HID + j0);
            float4* dst = (float4*)(sW + k * PW + g * 16);
            dst[0] = src[0]; dst[1] = src[1]; dst[2] = src[2]; dst[3] = src[3];
        }
    }

    const int erow = tid >> 4;
    const int jj   = tid & 15;
    const int len  = lengths[b0 + erow];
    float creg = 0.f, hreg = 0.f;
    const int kbase = w * 32;

    for (int t = 0; t < TS; ++t) {
        const float* __restrict__ hprev = g_hbuf[t & 1];
        float*       __restrict__ hnext = g_hbuf[(t + 1) & 1];

        const float* xrow = g_xwb + ((size_t)t * BSZ + b0 + erow) * 1024 + j0 + jj;
        float pf = __ldcg(xrow), pi = __ldcg(xrow + 256);
        float pc = __ldcg(xrow + 512), po = __ldcg(xrow + 768);

        #pragma unroll
        for (int it = 0; it < 4; ++it) {
            int idx = tid + it * 256;
            int r = idx >> 6, cc = idx & 63;
            float4 v = __ldcg((const float4*)(hprev + (size_t)(b0 + r) * HID + cc * 4));
            *(float4*)(sA + r * PA + cc * 4) = v;
        }
        __syncthreads();

        u64 acc[4][4];
        #pragma unroll
        for (int j = 0; j < 4; ++j) { acc[j][0] = 0; acc[j][1] = 0; acc[j][2] = 0; acc[j][3] = 0; }
        #pragma unroll
        for (int kb = 0; kb < 8; ++kb) {
            const int k = kbase + kb * 4;
            float4 a4[4];
            #pragma unroll
            for (int j = 0; j < 4; ++j)
                a4[j] = *(const float4*)(sA + (rthr + 4 * j) * PA + k);
            #pragma unroll
            for (int kk = 0; kk < 4; ++kk) {
                const float* wp = sW + (k + kk) * PW + cthr * 4;
                ulonglong2 w0 = *(const ulonglong2*)(wp);
                ulonglong2 w1 = *(const ulonglong2*)(wp + 32);
                #pragma unroll
                for (int j = 0; j < 4; ++j) {
                    float av = (kk == 0) ? a4[j].x : (kk == 1) ? a4[j].y : (kk == 2) ? a4[j].z : a4[j].w;
                    u64 ad = dup2(av);
                    acc[j][0] = ffma2(ad, w0.x, acc[j][0]);
                    acc[j][1] = ffma2(ad, w0.y, acc[j][1]);
                    acc[j][2] = ffma2(ad, w1.x, acc[j][2]);
                    acc[j][3] = ffma2(ad, w1.y, acc[j][3]);
                }
            }
        }
        __syncthreads();

        #pragma unroll
        for (int j = 0; j < 4; ++j) {
            float* base = sRed + (w * 16 + rthr + 4 * j) * PR + cthr * 4;
            ulonglong2 s0; s0.x = acc[j][0]; s0.y = acc[j][1];
            ulonglong2 s1; s1.x = acc[j][2]; s1.y = acc[j][3];
            *(ulonglong2*)(base)      = s0;
            *(ulonglong2*)(base + 32) = s1;
        }
        __syncthreads();

        {
            float fs = pf, is2 = pi, cs2 = pc, os2 = po;
            #pragma unroll
            for (int ww = 0; ww < 8; ++ww) {
                const float* rb = sRed + (ww * 16 + erow) * PR + jj;
                fs  += rb[0];
                is2 += rb[16];
                cs2 += rb[32];
                os2 += rb[48];
            }
            float fg = sigmoidf_(fs), ig = sigmoidf_(is2), og = sigmoidf_(os2);
            float cc = tanhf_(cs2);
            float cn = fg * creg + ig * cc;
            float hn = og * tanhf_(cn);
            if (t < len) { creg = cn; hreg = hn; }
            hnext[(size_t)(b0 + erow) * HID + j0 + jj] = hreg;
        }

        // row-group barrier (16 arrivals), release/acquire, no L1-flushing fence
        __syncthreads();
        if (tid == 0) {
            arrive_release(myctr);
            wait_target(myctr, 16u * (unsigned)(t + 1));
        }
        __syncthreads();
    }

    // one global barrier before the tail (tail reads arbitrary h rows)
    if (tid == 0) {
        arrive_release(&g_bar);
        wait_target(&g_bar, NCTA);
    }
    __syncthreads();

    // tail: y = h @ Wy + by, then copy h
    const float* __restrict__ hfin = g_hbuf[0];
    if (bid < 64) {
        const int row = bid * 4 + (tid >> 6);
        const int oc  = tid & 63;
        const float* hr = hfin + (size_t)row * HID;
        float acc = by[oc];
        #pragma unroll 4
        for (int k4 = 0; k4 < HID / 4; ++k4) {
            float4 hv = __ldcg((const float4*)(hr + k4 * 4));
            const float* wp = Wy + (size_t)k4 * 4 * OUTD + oc;
            acc += hv.x * wp[0] + hv.y * wp[OUTD] + hv.z * wp[2 * OUTD] + hv.w * wp[3 * OUTD];
        }
        out[(size_t)row * OUTD + oc] = acc;
    }
    {
        int idx = bid * 256 + tid;
        if (idx < BSZ * HID / 4) {
            float4 v = __ldcg(((const float4*)hfin) + idx);
            ((float4*)(out + BSZ * OUTD))[idx] = v;
        }
    }
}

extern "C" void kernel_launch(void* const* d_in, const int* in_sizes, int n_in,
                              void* d_out, int out_size) {
    const float* x       = (const float*)d_in[0];
    const int*   lengths = (const int*)  d_in[1];
    const float* Wf = (const float*)d_in[2];  const float* bf = (const float*)d_in[3];
    const float* Wi = (const float*)d_in[4];  const float* bi = (const float*)d_in[5];
    const float* Wc = (const float*)d_in[6];  const float* bc = (const float*)d_in[7];
    const float* Wo = (const float*)d_in[8];  const float* bo = (const float*)d_in[9];
    const float* Wy = (const float*)d_in[10]; const float* by = (const float*)d_in[11];
    float* out = (float*)d_out;

    cudaFuncSetAttribute(xw_mma, cudaFuncAttributeMaxDynamicSharedMemorySize, SMEM_MMA);
    cudaFuncSetAttribute(lstm_serial, cudaFuncAttributeMaxDynamicSharedMemorySize, SMEM_SERIAL);

    convert_x<<<(MROWS * DIN / 4) / 256, 256>>>(x);
    convert_w<<<1024, 256>>>(Wf, Wi, Wc, Wo);
    xw_mma<<<dim3(8, MROWS / 128), 256, SMEM_MMA>>>(bf, bi, bc, bo);
    init_state<<<64, 256>>>();
    lstm_serial<<<NCTA, 256, SMEM_SERIAL>>>(lengths, Wf, Wi, Wc, Wo, Wy, by, out);
}